// round 9
// baseline (speedup 1.0000x reference)
#include <cuda_runtime.h>
#include <math.h>

#define BS 8
#define QN 1000
#define NC 92
#define TN 300
#define QP1 1001
#define TP1 301
#define SCSZ (BS*QP1*TP1)          // 2,410,408
#define MTROW (QN+TN)              // 1300
#define CPL 10                     // columns per DP lane (30 lanes * 10 = 300)
#define CHUNK 250                  // traceback rows staged per smem load
#define NSTEP 1032                 // >= QN + 29 (drain), multiple of 4
#define FULLM 0xffffffffu
#define NEGINF (-INFINITY)

__device__ float g_prob[BS*QN*NC];
__device__ float g_rw[BS*QN*TN];             // reward = 10000 - cost
__device__ unsigned g_packed[BS*QP1*32];     // 2-bit ptr codes, 1 word per lane
__device__ int g_lbl64;                      // 1 if labels are int64, 0 if int32

// ---------------- label dtype detection ----------------
__global__ void detect_kernel(const unsigned* __restrict__ lbl_raw) {
    int allzero = 1;
    #pragma unroll
    for (int k = 1; k < 16; k += 2) allzero &= (lbl_raw[k] == 0u);
    g_lbl64 = allzero;
}

// ---------------- softmax over logits [BS*QN, NC] -> g_prob ----------------
__global__ void softmax_kernel(const float* __restrict__ logits) {
    int warpId = (blockIdx.x * blockDim.x + threadIdx.x) >> 5;
    int lane = threadIdx.x & 31;
    if (warpId >= BS * QN) return;
    const float* row = logits + warpId * NC;
    float v0 = (lane < NC)      ? row[lane]      : NEGINF;
    float v1 = (lane + 32 < NC) ? row[lane + 32] : NEGINF;
    float v2 = (lane + 64 < NC) ? row[lane + 64] : NEGINF;
    float m = fmaxf(v0, fmaxf(v1, v2));
    #pragma unroll
    for (int o = 16; o; o >>= 1) m = fmaxf(m, __shfl_xor_sync(FULLM, m, o));
    float e0 = (lane < NC)      ? expf(v0 - m) : 0.f;
    float e1 = (lane + 32 < NC) ? expf(v1 - m) : 0.f;
    float e2 = (lane + 64 < NC) ? expf(v2 - m) : 0.f;
    float s = e0 + e1 + e2;
    #pragma unroll
    for (int o = 16; o; o >>= 1) s += __shfl_xor_sync(FULLM, s, o);
    float* out = g_prob + warpId * NC;
    if (lane < NC)      out[lane]      = e0 / s;
    if (lane + 32 < NC) out[lane + 32] = e1 / s;
    if (lane + 64 < NC) out[lane + 64] = e2 / s;
}

// ---------------- cost matrix -> rewards [BS, QN, TN] ----------------
__global__ void cost_kernel(const float* __restrict__ pred_boxes,
                            const int* __restrict__ tgt_labels,
                            const float* __restrict__ tgt_boxes) {
    int idx = blockIdx.x * blockDim.x + threadIdx.x;
    if (idx >= BS * QN * TN) return;
    int t = idx % TN;
    int bq = idx / TN;
    int b = bq / QN;

    float4 pb = ((const float4*)pred_boxes)[bq];
    float4 tb = ((const float4*)tgt_boxes)[b * TN + t];
    int li = b * TN + t;
    int lbl = g_lbl64 ? tgt_labels[li * 2] : tgt_labels[li];
    lbl = max(0, min(NC - 1, lbl));
    float p = g_prob[bq * NC + lbl];

    float l1 = fabsf(pb.x - tb.x) + fabsf(pb.y - tb.y) +
               fabsf(pb.z - tb.z) + fabsf(pb.w - tb.w);

    float px1 = pb.x - 0.5f * pb.z, py1 = pb.y - 0.5f * pb.w;
    float px2 = pb.x + 0.5f * pb.z, py2 = pb.y + 0.5f * pb.w;
    float tx1 = tb.x - 0.5f * tb.z, ty1 = tb.y - 0.5f * tb.w;
    float tx2 = tb.x + 0.5f * tb.z, ty2 = tb.y + 0.5f * tb.w;

    float a1 = (px2 - px1) * (py2 - py1);
    float a2 = (tx2 - tx1) * (ty2 - ty1);
    float ltx = fmaxf(px1, tx1), lty = fmaxf(py1, ty1);
    float rbx = fminf(px2, tx2), rby = fminf(py2, ty2);
    float iw = fmaxf(rbx - ltx, 0.f), ih = fmaxf(rby - lty, 0.f);
    float inter = iw * ih;
    float uni = a1 + a2 - inter;
    float iou = inter / uni;
    float cx1 = fminf(px1, tx1), cy1 = fminf(py1, ty1);
    float cx2 = fmaxf(px2, tx2), cy2 = fmaxf(py2, ty2);
    float cw = fmaxf(cx2 - cx1, 0.f), ch = fmaxf(cy2 - cy1, 0.f);
    float ac = cw * ch;
    float giou = iou - (ac - uni) / ac;

    float cost = 5.0f * l1 - p - 2.0f * giou;
    g_rw[idx] = 10000.0f - cost;
}

// ---------------- DP + traceback: one WARP per batch, wavefront-skewed ----
// lane l processes row (step - l), columns [10l, 10l+10).
// Cross-lane traffic per step: 2 shfl (boundary score of current & prev row).
__global__ void __launch_bounds__(32, 1) dp_kernel(float* __restrict__ out) {
    __shared__ unsigned chunkBuf[CHUNK * 32];   // 32 KB

    int b = blockIdx.x;
    int lane = threadIdx.x;
    int base = lane * CPL;

    float* scores = out + (size_t)b * QP1 * TP1;
    unsigned* pkB = g_packed + (size_t)b * QP1 * 32;
    const float* rw = g_rw + (size_t)b * QN * TN;

    float prev[CPL];
    #pragma unroll
    for (int k = 0; k < CPL; k++) prev[k] = 0.f;
    float h1 = 0.f, h2 = 0.f;     // my sn[9] from 1 and 2 steps ago

    float2 B0[5], B1[5], B2[5], B3[5];

    #define LOADBUF(BUF, ROW)                                                   \
    {                                                                           \
        int rr = (ROW);                                                         \
        if (lane < 30 && rr >= 1 && rr <= QN) {                                 \
            const float2* pp = (const float2*)(rw + (size_t)(rr - 1) * TN + base); \
            _Pragma("unroll")                                                   \
            for (int q = 0; q < 5; q++) BUF[q] = pp[q];                         \
        }                                                                       \
    }

    LOADBUF(B0, 1 - lane)
    LOADBUF(B1, 2 - lane)
    LOADBUF(B2, 3 - lane)
    LOADBUF(B3, 4 - lane)

    #define STEP(S, BUF)                                                        \
    {                                                                           \
        int r = (S) - lane;                                                     \
        bool act = (lane < 30) && (r >= 1) && (r <= QN);                        \
        float X1 = __shfl_up_sync(FULLM, h1, 1);   /* s_r[base-1]      */       \
        float X2 = __shfl_up_sync(FULLM, h2, 1);   /* s_{r-1}[base-1]  */       \
        if (lane == 0) { X1 = NEGINF; X2 = 0.f; }                               \
        float rk[CPL];                                                          \
        _Pragma("unroll")                                                       \
        for (int q = 0; q < 5; q++) { rk[2*q] = BUF[q].x; rk[2*q+1] = BUF[q].y; } \
        LOADBUF(BUF, r + 4)        /* prefetch row consumed 4 steps later */    \
        float dg[CPL], m[CPL];                                                  \
        dg[0] = X2 + rk[0];                                                     \
        _Pragma("unroll")                                                       \
        for (int k = 1; k < CPL; k++) dg[k] = prev[k-1] + rk[k];                \
        _Pragma("unroll")                                                       \
        for (int k = 0; k < CPL; k++) m[k] = fmaxf(dg[k], prev[k]);             \
        float p1_[CPL], p2_[CPL], p4_[CPL], pf[CPL];                            \
        p1_[0] = m[0];                                                          \
        _Pragma("unroll")                                                       \
        for (int k = 1; k < CPL; k++) p1_[k] = fmaxf(m[k], m[k-1]);             \
        p2_[0] = p1_[0]; p2_[1] = p1_[1];                                       \
        _Pragma("unroll")                                                       \
        for (int k = 2; k < CPL; k++) p2_[k] = fmaxf(p1_[k], p1_[k-2]);         \
        _Pragma("unroll")                                                       \
        for (int k = 0; k < 4; k++) p4_[k] = p2_[k];                            \
        _Pragma("unroll")                                                       \
        for (int k = 4; k < CPL; k++) p4_[k] = fmaxf(p2_[k], p2_[k-4]);         \
        _Pragma("unroll")                                                       \
        for (int k = 0; k < 8; k++) pf[k] = p4_[k];                             \
        _Pragma("unroll")                                                       \
        for (int k = 8; k < CPL; k++) pf[k] = fmaxf(p4_[k], p4_[k-8]);          \
        float sn[CPL];                                                          \
        _Pragma("unroll")                                                       \
        for (int k = 0; k < CPL; k++) sn[k] = fmaxf(pf[k], X1);                 \
        h2 = h1;                                                                \
        if (act) {                                                              \
            unsigned word = 0;                                                  \
            float* dst = scores + (size_t)r * TP1 + 1 + base;                   \
            _Pragma("unroll")                                                   \
            for (int k = 0; k < CPL; k++) {                                     \
                unsigned e = (dg[k] == sn[k]) ? 0u : ((prev[k] == sn[k]) ? 1u : 2u); \
                word |= e << (2 * k);                                           \
                dst[k] = sn[k];                                                 \
            }                                                                   \
            pkB[(size_t)r * 32 + lane] = word;                                  \
            _Pragma("unroll")                                                   \
            for (int k = 0; k < CPL; k++) prev[k] = sn[k];                      \
            h1 = sn[CPL-1];                                                     \
        } else {                                                                \
            h1 = 0.f;    /* boundary row 0 for lanes not yet started */         \
        }                                                                       \
    }

    #pragma unroll 1
    for (int s = 1; s <= NSTEP; s += 4) {
        STEP(s,     B0)
        STEP(s + 1, B1)
        STEP(s + 2, B2)
        STEP(s + 3, B3)
    }
    #undef STEP
    #undef LOADBUF

    __threadfence_block();
    __syncwarp();

    // ---- traceback, chunked through smem ----
    float* mt = out + 2 * (size_t)SCSZ + (size_t)b * MTROW * 2;
    int r = QN, c = TN, st = 0;

    #pragma unroll 1
    for (int k = 0; k < QN / CHUNK; k++) {
        int hi = QN - k * CHUNK;
        int lo = hi - (CHUNK - 1);
        const unsigned* src = pkB + (size_t)lo * 32;
        #pragma unroll 4
        for (int x = lane; x < CHUNK * 32; x += 32) chunkBuf[x] = src[x];
        __syncwarp();
        if (lane == 0) {
            while (st < MTROW && r >= lo) {
                int p;
                if (c == 0) {
                    p = -1;
                } else {
                    int ci = c - 1;
                    unsigned wd = chunkBuf[(r - lo) * 32 + ci / CPL];
                    int e = (wd >> (2 * (ci % CPL))) & 3;
                    p = (e == 0) ? 0 : ((e == 1) ? -1 : 1);
                }
                int nr = (p == 1) ? r : r - 1;
                int nc = (p == -1) ? c : c - 1;
                bool ismatch = (p == 0);
                int oidx = (MTROW - 1 - st) * 2;
                mt[oidx]     = ismatch ? (float)nr : -1.f;
                mt[oidx + 1] = ismatch ? (float)nc : -1.f;
                r = nr; c = nc; st++;
            }
        }
        __syncwarp();
    }
    if (lane == 0) {
        while (st < MTROW) {
            int oidx = (MTROW - 1 - st) * 2;
            mt[oidx] = -1.f;
            mt[oidx + 1] = -1.f;
            st++;
        }
    }
}

// ---------------- pointers + score boundaries from packed codes ----------------
__global__ void recon_kernel(float* __restrict__ out) {
    int idx = blockIdx.x * blockDim.x + threadIdx.x;
    if (idx >= BS * QP1 * TP1) return;
    int j = idx % TP1;
    int bi = idx / TP1;
    int i = bi % QP1;
    int b = bi / QP1;

    float pv;
    if (i == 0) {
        pv = (j == 0) ? 0.f : 1.f;
    } else if (j == 0) {
        pv = -1.f;
    } else {
        int ci = j - 1;
        unsigned wd = g_packed[((size_t)b * QP1 + i) * 32 + ci / CPL];
        unsigned e = (wd >> (2 * (ci % CPL))) & 3u;
        pv = (e == 0u) ? 0.f : ((e == 1u) ? -1.f : 1.f);
    }
    out[SCSZ + (size_t)idx] = pv;
    if (i == 0 || j == 0) out[idx] = 0.f;     // score boundaries
}

extern "C" void kernel_launch(void* const* d_in, const int* in_sizes, int n_in,
                              void* d_out, int out_size) {
    const float* pred_logits = (const float*)d_in[0];
    const float* pred_boxes  = (const float*)d_in[1];
    const int*   tgt_labels  = (const int*)d_in[2];
    const float* tgt_boxes   = (const float*)d_in[3];
    float* out = (float*)d_out;

    detect_kernel<<<1, 1>>>((const unsigned*)d_in[2]);
    softmax_kernel<<<(BS * QN + 7) / 8, 256>>>(pred_logits);
    cost_kernel<<<(BS * QN * TN + 255) / 256, 256>>>(pred_boxes, tgt_labels, tgt_boxes);
    dp_kernel<<<BS, 32>>>(out);
    recon_kernel<<<(BS * QP1 * TP1 + 255) / 256, 256>>>(out);
}

// round 10
// speedup vs baseline: 1.1938x; 1.1938x over previous
#include <cuda_runtime.h>
#include <math.h>

#define BS 8
#define QN 1000
#define NC 92
#define TN 300
#define QP1 1001
#define TP1 301
#define SCSZ (BS*QP1*TP1)          // 2,410,408
#define MTROW (QN+TN)              // 1300
#define CPL 10                     // columns per DP lane (30 lanes * 10 = 300)
#define CHUNK 250                  // traceback rows per smem stage
#define NSTEP 1032                 // >= QN + 30 (drain), multiple of 4
#define SKROW 1040                 // skewed rows allocated (>= NSTEP + 4 prefetch)
#define FULLM 0xffffffffu
#define NEGINF (-INFINITY)

__device__ float g_prob[BS*QN*NC];
__device__ float g_rwsk[BS*SKROW*320];       // rewards, skewed: [b][r+l][k*32+l]
__device__ float g_scr[BS*SKROW*320];        // scores scratch, skewed by step
__device__ unsigned g_pk2[BS*SKROW*32];      // 2-bit ptr codes, skewed by step
__device__ int g_lbl64;

// ---------------- label dtype detection ----------------
__global__ void detect_kernel(const unsigned* __restrict__ lbl_raw) {
    int allzero = 1;
    #pragma unroll
    for (int k = 1; k < 16; k += 2) allzero &= (lbl_raw[k] == 0u);
    g_lbl64 = allzero;
}

// ---------------- softmax over logits [BS*QN, NC] -> g_prob ----------------
__global__ void softmax_kernel(const float* __restrict__ logits) {
    int warpId = (blockIdx.x * blockDim.x + threadIdx.x) >> 5;
    int lane = threadIdx.x & 31;
    if (warpId >= BS * QN) return;
    const float* row = logits + warpId * NC;
    float v0 = (lane < NC)      ? row[lane]      : NEGINF;
    float v1 = (lane + 32 < NC) ? row[lane + 32] : NEGINF;
    float v2 = (lane + 64 < NC) ? row[lane + 64] : NEGINF;
    float m = fmaxf(v0, fmaxf(v1, v2));
    #pragma unroll
    for (int o = 16; o; o >>= 1) m = fmaxf(m, __shfl_xor_sync(FULLM, m, o));
    float e0 = (lane < NC)      ? expf(v0 - m) : 0.f;
    float e1 = (lane + 32 < NC) ? expf(v1 - m) : 0.f;
    float e2 = (lane + 64 < NC) ? expf(v2 - m) : 0.f;
    float s = e0 + e1 + e2;
    #pragma unroll
    for (int o = 16; o; o >>= 1) s += __shfl_xor_sync(FULLM, s, o);
    float* out = g_prob + warpId * NC;
    if (lane < NC)      out[lane]      = e0 / s;
    if (lane + 32 < NC) out[lane + 32] = e1 / s;
    if (lane + 64 < NC) out[lane + 64] = e2 / s;
}

// ---------------- cost matrix -> skewed rewards ----------------
__global__ void cost_kernel(const float* __restrict__ pred_boxes,
                            const int* __restrict__ tgt_labels,
                            const float* __restrict__ tgt_boxes) {
    int idx = blockIdx.x * blockDim.x + threadIdx.x;
    if (idx >= BS * QN * TN) return;
    int t = idx % TN;
    int bq = idx / TN;
    int b = bq / QN;
    int r = (bq % QN) + 1;       // DP row 1..QN

    float4 pb = ((const float4*)pred_boxes)[bq];
    float4 tb = ((const float4*)tgt_boxes)[b * TN + t];
    int li = b * TN + t;
    int lbl = g_lbl64 ? tgt_labels[li * 2] : tgt_labels[li];
    lbl = max(0, min(NC - 1, lbl));
    float p = g_prob[bq * NC + lbl];

    float l1 = fabsf(pb.x - tb.x) + fabsf(pb.y - tb.y) +
               fabsf(pb.z - tb.z) + fabsf(pb.w - tb.w);

    float px1 = pb.x - 0.5f * pb.z, py1 = pb.y - 0.5f * pb.w;
    float px2 = pb.x + 0.5f * pb.z, py2 = pb.y + 0.5f * pb.w;
    float tx1 = tb.x - 0.5f * tb.z, ty1 = tb.y - 0.5f * tb.w;
    float tx2 = tb.x + 0.5f * tb.z, ty2 = tb.y + 0.5f * tb.w;

    float a1 = (px2 - px1) * (py2 - py1);
    float a2 = (tx2 - tx1) * (ty2 - ty1);
    float ltx = fmaxf(px1, tx1), lty = fmaxf(py1, ty1);
    float rbx = fminf(px2, tx2), rby = fminf(py2, ty2);
    float iw = fmaxf(rbx - ltx, 0.f), ih = fmaxf(rby - lty, 0.f);
    float inter = iw * ih;
    float uni = a1 + a2 - inter;
    float iou = inter / uni;
    float cx1 = fminf(px1, tx1), cy1 = fminf(py1, ty1);
    float cx2 = fmaxf(px2, tx2), cy2 = fmaxf(py2, ty2);
    float cw = fmaxf(cx2 - cx1, 0.f), ch = fmaxf(cy2 - cy1, 0.f);
    float ac = cw * ch;
    float giou = iou - (ac - uni) / ac;

    float cost = 5.0f * l1 - p - 2.0f * giou;
    // skewed store: consumed by lane l = t/10 at step s = r + l, slot k*32 + l
    int l = t / CPL, k = t % CPL;
    g_rwsk[(size_t)b * SKROW * 320 + (size_t)(r + l) * 320 + k * 32 + l] = 10000.0f - cost;
}

// ---------------- DP + traceback: one WARP per batch, wavefront-skewed ----
// All gmem accesses coalesced via step-indexed skewed layouts.
__global__ void __launch_bounds__(32, 1) dp_kernel(float* __restrict__ out) {
    __shared__ unsigned chunkBuf[(CHUNK + 30) * 32];   // 35.8 KB

    int b = blockIdx.x;
    int lane = threadIdx.x;

    const float* rwsk = g_rwsk + (size_t)b * SKROW * 320;
    float* scr = g_scr + (size_t)b * SKROW * 320;
    unsigned* pk2 = g_pk2 + (size_t)b * SKROW * 32;

    float prev[CPL];
    #pragma unroll
    for (int k = 0; k < CPL; k++) prev[k] = 0.f;
    float h1 = 0.f, h2 = 0.f;

    float B0[CPL], B1[CPL], B2[CPL], B3[CPL];

    #define LOADBUF(BUF, S)                                                     \
    {                                                                           \
        const float* pp = rwsk + (size_t)(S) * 320 + lane;                      \
        _Pragma("unroll")                                                       \
        for (int k = 0; k < CPL; k++) BUF[k] = pp[k * 32];                      \
    }

    LOADBUF(B0, 1)
    LOADBUF(B1, 2)
    LOADBUF(B2, 3)
    LOADBUF(B3, 4)

    #define STEP(S, BUF)                                                        \
    {                                                                           \
        int r = (S) - lane;                                                     \
        bool act = (lane < 30) && (r >= 1) && (r <= QN);                        \
        float X1 = __shfl_up_sync(FULLM, h1, 1);   /* s_r[base-1]      */       \
        float X2 = __shfl_up_sync(FULLM, h2, 1);   /* s_{r-1}[base-1]  */       \
        if (lane == 0) { X1 = NEGINF; X2 = 0.f; }                               \
        float rk[CPL];                                                          \
        _Pragma("unroll")                                                       \
        for (int k = 0; k < CPL; k++) rk[k] = BUF[k];                           \
        LOADBUF(BUF, (S) + 4)      /* prefetch step consumed 4 steps later */   \
        float dg[CPL], m[CPL];                                                  \
        dg[0] = X2 + rk[0];                                                     \
        _Pragma("unroll")                                                       \
        for (int k = 1; k < CPL; k++) dg[k] = prev[k-1] + rk[k];                \
        _Pragma("unroll")                                                       \
        for (int k = 0; k < CPL; k++) m[k] = fmaxf(dg[k], prev[k]);             \
        float p1_[CPL], p2_[CPL], p4_[CPL], pf[CPL];                            \
        p1_[0] = m[0];                                                          \
        _Pragma("unroll")                                                       \
        for (int k = 1; k < CPL; k++) p1_[k] = fmaxf(m[k], m[k-1]);             \
        p2_[0] = p1_[0]; p2_[1] = p1_[1];                                       \
        _Pragma("unroll")                                                       \
        for (int k = 2; k < CPL; k++) p2_[k] = fmaxf(p1_[k], p1_[k-2]);         \
        _Pragma("unroll")                                                       \
        for (int k = 0; k < 4; k++) p4_[k] = p2_[k];                            \
        _Pragma("unroll")                                                       \
        for (int k = 4; k < CPL; k++) p4_[k] = fmaxf(p2_[k], p2_[k-4]);         \
        _Pragma("unroll")                                                       \
        for (int k = 0; k < 8; k++) pf[k] = p4_[k];                             \
        _Pragma("unroll")                                                       \
        for (int k = 8; k < CPL; k++) pf[k] = fmaxf(p4_[k], p4_[k-8]);          \
        float sn[CPL];                                                          \
        _Pragma("unroll")                                                       \
        for (int k = 0; k < CPL; k++) sn[k] = fmaxf(pf[k], X1);                 \
        h2 = h1;                                                                \
        unsigned word = 0;                                                      \
        float* dsc = scr + (size_t)(S) * 320 + lane;                            \
        _Pragma("unroll")                                                       \
        for (int k = 0; k < CPL; k++) {                                         \
            unsigned e = (dg[k] == sn[k]) ? 0u : ((prev[k] == sn[k]) ? 1u : 2u);\
            word |= e << (2 * k);                                               \
            dsc[k * 32] = sn[k];       /* coalesced: 1 line per STG */          \
        }                                                                       \
        pk2[(size_t)(S) * 32 + lane] = word;                                    \
        if (act) {                                                              \
            _Pragma("unroll")                                                   \
            for (int k = 0; k < CPL; k++) prev[k] = sn[k];                      \
            h1 = sn[CPL-1];                                                     \
        } else {                                                                \
            h1 = 0.f;                                                           \
        }                                                                       \
    }

    #pragma unroll 1
    for (int s = 1; s <= NSTEP; s += 4) {
        STEP(s,     B0)
        STEP(s + 1, B1)
        STEP(s + 2, B2)
        STEP(s + 3, B3)
    }
    #undef STEP
    #undef LOADBUF

    __threadfence_block();
    __syncwarp();

    // ---- traceback: stage pk2 linearly (coalesced), chase in smem ----
    float* mt = out + 2 * (size_t)SCSZ + (size_t)b * MTROW * 2;
    int r = QN, c = TN, st = 0;

    #pragma unroll 1
    for (int kk = 0; kk < QN / CHUNK; kk++) {
        int hi = QN - kk * CHUNK;
        int lo = hi - (CHUNK - 1);
        const unsigned* src = pk2 + (size_t)lo * 32;
        #pragma unroll 4
        for (int x = lane; x < (CHUNK + 30) * 32; x += 32) chunkBuf[x] = src[x];
        __syncwarp();
        if (lane == 0) {
            while (st < MTROW && r >= lo) {
                int p;
                if (c == 0) {
                    p = -1;
                } else {
                    int ci = c - 1;
                    int l = ci / CPL;
                    unsigned wd = chunkBuf[(r + l - lo) * 32 + l];
                    int e = (wd >> (2 * (ci % CPL))) & 3;
                    p = (e == 0) ? 0 : ((e == 1) ? -1 : 1);
                }
                int nr = (p == 1) ? r : r - 1;
                int nc = (p == -1) ? c : c - 1;
                bool ismatch = (p == 0);
                int oidx = (MTROW - 1 - st) * 2;
                mt[oidx]     = ismatch ? (float)nr : -1.f;
                mt[oidx + 1] = ismatch ? (float)nc : -1.f;
                r = nr; c = nc; st++;
            }
        }
        __syncwarp();
    }
    if (lane == 0) {
        while (st < MTROW) {
            int oidx = (MTROW - 1 - st) * 2;
            mt[oidx] = -1.f;
            mt[oidx + 1] = -1.f;
            st++;
        }
    }
}

// ---------------- de-skew scores + pointers into out ----------------
__global__ void recon_kernel(float* __restrict__ out) {
    int idx = blockIdx.x * blockDim.x + threadIdx.x;
    if (idx >= BS * QP1 * TP1) return;
    int j = idx % TP1;
    int bi = idx / TP1;
    int i = bi % QP1;
    int b = bi / QP1;

    float sv, pv;
    if (i == 0) {
        sv = 0.f;
        pv = (j == 0) ? 0.f : 1.f;
    } else if (j == 0) {
        sv = 0.f;
        pv = -1.f;
    } else {
        int ci = j - 1;
        int l = ci / CPL, k = ci % CPL;
        size_t s = (size_t)(i + l);
        sv = g_scr[(size_t)b * SKROW * 320 + s * 320 + k * 32 + l];
        unsigned wd = g_pk2[(size_t)b * SKROW * 32 + s * 32 + l];
        unsigned e = (wd >> (2 * k)) & 3u;
        pv = (e == 0u) ? 0.f : ((e == 1u) ? -1.f : 1.f);
    }
    out[idx] = sv;
    out[SCSZ + (size_t)idx] = pv;
}

extern "C" void kernel_launch(void* const* d_in, const int* in_sizes, int n_in,
                              void* d_out, int out_size) {
    const float* pred_logits = (const float*)d_in[0];
    const float* pred_boxes  = (const float*)d_in[1];
    const int*   tgt_labels  = (const int*)d_in[2];
    const float* tgt_boxes   = (const float*)d_in[3];
    float* out = (float*)d_out;

    detect_kernel<<<1, 1>>>((const unsigned*)d_in[2]);
    softmax_kernel<<<(BS * QN + 7) / 8, 256>>>(pred_logits);
    cost_kernel<<<(BS * QN * TN + 255) / 256, 256>>>(pred_boxes, tgt_labels, tgt_boxes);
    dp_kernel<<<BS, 32>>>(out);
    recon_kernel<<<(BS * QP1 * TP1 + 255) / 256, 256>>>(out);
}

// round 12
// speedup vs baseline: 1.3850x; 1.1601x over previous
#include <cuda_runtime.h>
#include <math.h>

#define BS 8
#define QN 1000
#define NC 92
#define TN 300
#define QP1 1001
#define TP1 301
#define SCSZ (BS*QP1*TP1)          // 2,410,408
#define MTROW (QN+TN)              // 1300
#define CPL 10
#define CHUNK 250
#define NSTEP 1032                 // = 8*129 >= QN+30 drain
#define SKROW 1048                 // >= NSTEP + 8 prefetch
#define FULLM 0xffffffffu
#define NEGINF (-INFINITY)
// slot of (strip col k, lane l) within a 320-float step row (float2-paired)
#define SLOT(k,l) (((k) >> 1) * 64 + (l) * 2 + ((k) & 1))

__device__ float g_prob[BS*QN*NC];
__device__ float g_rwsk[BS*SKROW*320];       // rewards, skewed+paired
__device__ float g_scr[BS*SKROW*320];        // scores scratch, skewed+paired
__device__ unsigned g_pk2[BS*SKROW*32];      // 2-bit ptr codes (by code_kernel)
__device__ int g_lbl64;

// ---------------- label dtype detection ----------------
__global__ void detect_kernel(const unsigned* __restrict__ lbl_raw) {
    int allzero = 1;
    #pragma unroll
    for (int k = 1; k < 16; k += 2) allzero &= (lbl_raw[k] == 0u);
    g_lbl64 = allzero;
}

// ---------------- softmax ----------------
__global__ void softmax_kernel(const float* __restrict__ logits) {
    int warpId = (blockIdx.x * blockDim.x + threadIdx.x) >> 5;
    int lane = threadIdx.x & 31;
    if (warpId >= BS * QN) return;
    const float* row = logits + warpId * NC;
    float v0 = (lane < NC)      ? row[lane]      : NEGINF;
    float v1 = (lane + 32 < NC) ? row[lane + 32] : NEGINF;
    float v2 = (lane + 64 < NC) ? row[lane + 64] : NEGINF;
    float m = fmaxf(v0, fmaxf(v1, v2));
    #pragma unroll
    for (int o = 16; o; o >>= 1) m = fmaxf(m, __shfl_xor_sync(FULLM, m, o));
    float e0 = (lane < NC)      ? expf(v0 - m) : 0.f;
    float e1 = (lane + 32 < NC) ? expf(v1 - m) : 0.f;
    float e2 = (lane + 64 < NC) ? expf(v2 - m) : 0.f;
    float s = e0 + e1 + e2;
    #pragma unroll
    for (int o = 16; o; o >>= 1) s += __shfl_xor_sync(FULLM, s, o);
    float* out = g_prob + warpId * NC;
    if (lane < NC)      out[lane]      = e0 / s;
    if (lane + 32 < NC) out[lane + 32] = e1 / s;
    if (lane + 64 < NC) out[lane + 64] = e2 / s;
}

// ---------------- cost -> skewed paired rewards ----------------
__global__ void cost_kernel(const float* __restrict__ pred_boxes,
                            const int* __restrict__ tgt_labels,
                            const float* __restrict__ tgt_boxes) {
    int idx = blockIdx.x * blockDim.x + threadIdx.x;
    if (idx >= BS * QN * TN) return;
    int t = idx % TN;
    int bq = idx / TN;
    int b = bq / QN;
    int r = (bq % QN) + 1;

    float4 pb = ((const float4*)pred_boxes)[bq];
    float4 tb = ((const float4*)tgt_boxes)[b * TN + t];
    int li = b * TN + t;
    int lbl = g_lbl64 ? tgt_labels[li * 2] : tgt_labels[li];
    lbl = max(0, min(NC - 1, lbl));
    float p = g_prob[bq * NC + lbl];

    float l1 = fabsf(pb.x - tb.x) + fabsf(pb.y - tb.y) +
               fabsf(pb.z - tb.z) + fabsf(pb.w - tb.w);

    float px1 = pb.x - 0.5f * pb.z, py1 = pb.y - 0.5f * pb.w;
    float px2 = pb.x + 0.5f * pb.z, py2 = pb.y + 0.5f * pb.w;
    float tx1 = tb.x - 0.5f * tb.z, ty1 = tb.y - 0.5f * tb.w;
    float tx2 = tb.x + 0.5f * tb.z, ty2 = tb.y + 0.5f * tb.w;

    float a1 = (px2 - px1) * (py2 - py1);
    float a2 = (tx2 - tx1) * (ty2 - ty1);
    float ltx = fmaxf(px1, tx1), lty = fmaxf(py1, ty1);
    float rbx = fminf(px2, tx2), rby = fminf(py2, ty2);
    float iw = fmaxf(rbx - ltx, 0.f), ih = fmaxf(rby - lty, 0.f);
    float inter = iw * ih;
    float uni = a1 + a2 - inter;
    float iou = inter / uni;
    float cx1 = fminf(px1, tx1), cy1 = fminf(py1, ty1);
    float cx2 = fmaxf(px2, tx2), cy2 = fmaxf(py2, ty2);
    float cw = fmaxf(cx2 - cx1, 0.f), ch = fmaxf(cy2 - cy1, 0.f);
    float ac = cw * ch;
    float giou = iou - (ac - uni) / ac;

    float cost = 5.0f * l1 - p - 2.0f * giou;
    int l = t / CPL, k = t % CPL;
    g_rwsk[(size_t)b * SKROW * 320 + (size_t)(r + l) * 320 + SLOT(k, l)] = 10000.0f - cost;
}

// ---------------- DP: one WARP per batch, wavefront, scores only ----------
__global__ void __launch_bounds__(32, 1) dp_kernel() {
    int b = blockIdx.x;
    int lane = threadIdx.x;

    const float2* rwsk = (const float2*)(g_rwsk + (size_t)b * SKROW * 320);
    float2* scr = (float2*)(g_scr + (size_t)b * SKROW * 320);

    float prev[CPL];
    #pragma unroll
    for (int k = 0; k < CPL; k++) prev[k] = 0.f;
    float h1 = 0.f, h2 = 0.f;

    float2 B0[5], B1[5], B2[5], B3[5], B4[5], B5[5], B6[5], B7[5];

    #define LOADBUF(BUF, S)                                                     \
    {                                                                           \
        const float2* pp = rwsk + (size_t)(S) * 160 + lane;                     \
        _Pragma("unroll")                                                       \
        for (int q = 0; q < 5; q++) BUF[q] = pp[q * 32];                        \
    }

    LOADBUF(B0, 1) LOADBUF(B1, 2) LOADBUF(B2, 3) LOADBUF(B3, 4)
    LOADBUF(B4, 5) LOADBUF(B5, 6) LOADBUF(B6, 7) LOADBUF(B7, 8)

    #define STEP(S, BUF)                                                        \
    {                                                                           \
        int r = (S) - lane;                                                     \
        bool act = (lane < 30) && (r >= 1) && (r <= QN);                        \
        float X1 = __shfl_up_sync(FULLM, h1, 1);                                \
        float X2 = __shfl_up_sync(FULLM, h2, 1);                                \
        if (lane == 0) { X1 = NEGINF; X2 = 0.f; }                               \
        float rk[CPL];                                                          \
        _Pragma("unroll")                                                       \
        for (int q = 0; q < 5; q++) { rk[2*q] = BUF[q].x; rk[2*q+1] = BUF[q].y; } \
        LOADBUF(BUF, (S) + 8)                                                   \
        float dg[CPL], m[CPL];                                                  \
        dg[0] = X2 + rk[0];                                                     \
        _Pragma("unroll")                                                       \
        for (int k = 1; k < CPL; k++) dg[k] = prev[k-1] + rk[k];                \
        _Pragma("unroll")                                                       \
        for (int k = 0; k < CPL; k++) m[k] = fmaxf(dg[k], prev[k]);             \
        m[0] = fmaxf(m[0], X1);   /* fold left-boundary into prefix head */     \
        float p1_[CPL], p2_[CPL], p4_[CPL], pf[CPL];                            \
        p1_[0] = m[0];                                                          \
        _Pragma("unroll")                                                       \
        for (int k = 1; k < CPL; k++) p1_[k] = fmaxf(m[k], m[k-1]);             \
        p2_[0] = p1_[0]; p2_[1] = p1_[1];                                       \
        _Pragma("unroll")                                                       \
        for (int k = 2; k < CPL; k++) p2_[k] = fmaxf(p1_[k], p1_[k-2]);         \
        _Pragma("unroll")                                                       \
        for (int k = 0; k < 4; k++) p4_[k] = p2_[k];                            \
        _Pragma("unroll")                                                       \
        for (int k = 4; k < CPL; k++) p4_[k] = fmaxf(p2_[k], p2_[k-4]);         \
        _Pragma("unroll")                                                       \
        for (int k = 0; k < 8; k++) pf[k] = p4_[k];                             \
        _Pragma("unroll")                                                       \
        for (int k = 8; k < CPL; k++) pf[k] = fmaxf(p4_[k], p4_[k-8]);          \
        h2 = h1;                                                                \
        float2* dsc = scr + (size_t)(S) * 160 + lane;                           \
        _Pragma("unroll")                                                       \
        for (int q = 0; q < 5; q++) dsc[q * 32] = make_float2(pf[2*q], pf[2*q+1]); \
        if (act) {                                                              \
            _Pragma("unroll")                                                   \
            for (int k = 0; k < CPL; k++) prev[k] = pf[k];                      \
            h1 = pf[CPL-1];                                                     \
        } else {                                                                \
            h1 = 0.f;                                                           \
        }                                                                       \
    }

    #pragma unroll 1
    for (int s = 1; s <= NSTEP; s += 8) {
        STEP(s,     B0) STEP(s + 1, B1) STEP(s + 2, B2) STEP(s + 3, B3)
        STEP(s + 4, B4) STEP(s + 5, B5) STEP(s + 6, B6) STEP(s + 7, B7)
    }
    #undef STEP
    #undef LOADBUF
}

// ---------------- codes from scores+rewards (bit-identical decisions) ------
// one thread per (b, row r, lane l): 10 codes -> packed word + ptr floats
__global__ void code_kernel(float* __restrict__ out) {
    int idx = blockIdx.x * blockDim.x + threadIdx.x;
    if (idx >= BS * QN * 30) return;
    int l = idx % 30;
    int br = idx / 30;
    int r = (br % QN) + 1;
    int b = br / QN;

    const float* scr = g_scr + (size_t)b * SKROW * 320;
    const float* rwsk = g_rwsk + (size_t)b * SKROW * 320;
    size_t sc = (size_t)(r + l) * 320;        // step of (r, l)
    size_t sp = (size_t)(r - 1 + l) * 320;    // step of (r-1, l)

    float X2;
    if (l == 0) X2 = 0.f;
    else if (r == 1) X2 = 0.f;
    else X2 = scr[(size_t)(r - 1 + l - 1) * 320 + SLOT(9, l - 1)];

    float* dst = out + SCSZ + ((size_t)b * QP1 + r) * TP1 + 1 + l * CPL;
    unsigned word = 0;
    float pl = X2;
    #pragma unroll
    for (int k = 0; k < CPL; k++) {
        float rw = rwsk[sc + SLOT(k, l)];
        float pv = (r == 1) ? 0.f : scr[sp + SLOT(k, l)];
        float sn = scr[sc + SLOT(k, l)];
        float dg = pl + rw;
        unsigned e = (dg == sn) ? 0u : ((pv == sn) ? 1u : 2u);
        word |= e << (2 * k);
        dst[k] = (e == 0u) ? 0.f : ((e == 1u) ? -1.f : 1.f);
        pl = pv;
    }
    g_pk2[(size_t)b * SKROW * 32 + (size_t)(r + l) * 32 + l] = word;
}

// ---------------- de-skew scores + boundary pointers ----------------
__global__ void recon_kernel(float* __restrict__ out) {
    int idx = blockIdx.x * blockDim.x + threadIdx.x;
    if (idx >= BS * QP1 * TP1) return;
    int j = idx % TP1;
    int bi = idx / TP1;
    int i = bi % QP1;
    int b = bi / QP1;

    if (i == 0) {
        out[idx] = 0.f;
        out[SCSZ + (size_t)idx] = (j == 0) ? 0.f : 1.f;
    } else if (j == 0) {
        out[idx] = 0.f;
        out[SCSZ + (size_t)idx] = -1.f;
    } else {
        int ci = j - 1;
        int l = ci / CPL, k = ci % CPL;
        out[idx] = g_scr[(size_t)b * SKROW * 320 + (size_t)(i + l) * 320 + SLOT(k, l)];
    }
}

// ---------------- traceback: one warp per batch, chunked smem ----------
__global__ void __launch_bounds__(32, 1) tb_kernel(float* __restrict__ out) {
    __shared__ unsigned chunkBuf[(CHUNK + 30) * 32];   // 35.8 KB

    int b = blockIdx.x;
    int lane = threadIdx.x;
    const unsigned* pk2 = g_pk2 + (size_t)b * SKROW * 32;
    float* mt = out + 2 * (size_t)SCSZ + (size_t)b * MTROW * 2;
    int r = QN, c = TN, st = 0;

    #pragma unroll 1
    for (int kk = 0; kk < QN / CHUNK; kk++) {
        int hi = QN - kk * CHUNK;
        int lo = hi - (CHUNK - 1);
        const unsigned* src = pk2 + (size_t)lo * 32;
        #pragma unroll 4
        for (int x = lane; x < (CHUNK + 30) * 32; x += 32) chunkBuf[x] = src[x];
        __syncwarp();
        if (lane == 0) {
            while (st < MTROW && r >= lo) {
                int p;
                if (c == 0) {
                    p = -1;
                } else {
                    int ci = c - 1;
                    int l = ci / CPL;
                    unsigned wd = chunkBuf[(r + l - lo) * 32 + l];
                    int e = (wd >> (2 * (ci % CPL))) & 3;
                    p = (e == 0) ? 0 : ((e == 1) ? -1 : 1);
                }
                int nr = (p == 1) ? r : r - 1;
                int nc = (p == -1) ? c : c - 1;
                bool ismatch = (p == 0);
                int oidx = (MTROW - 1 - st) * 2;
                mt[oidx]     = ismatch ? (float)nr : -1.f;
                mt[oidx + 1] = ismatch ? (float)nc : -1.f;
                r = nr; c = nc; st++;
            }
        }
        __syncwarp();
    }
    if (lane == 0) {
        while (st < MTROW) {
            int oidx = (MTROW - 1 - st) * 2;
            mt[oidx] = -1.f;
            mt[oidx + 1] = -1.f;
            st++;
        }
    }
}

extern "C" void kernel_launch(void* const* d_in, const int* in_sizes, int n_in,
                              void* d_out, int out_size) {
    const float* pred_logits = (const float*)d_in[0];
    const float* pred_boxes  = (const float*)d_in[1];
    const int*   tgt_labels  = (const int*)d_in[2];
    const float* tgt_boxes   = (const float*)d_in[3];
    float* out = (float*)d_out;

    detect_kernel<<<1, 1>>>((const unsigned*)d_in[2]);
    softmax_kernel<<<(BS * QN + 7) / 8, 256>>>(pred_logits);
    cost_kernel<<<(BS * QN * TN + 255) / 256, 256>>>(pred_boxes, tgt_labels, tgt_boxes);
    dp_kernel<<<BS, 32>>>();
    recon_kernel<<<(BS * QP1 * TP1 + 255) / 256, 256>>>(out);
    code_kernel<<<(BS * QN * 30 + 127) / 128, 128>>>(out);
    tb_kernel<<<BS, 32>>>(out);
}

// round 13
// speedup vs baseline: 1.3946x; 1.0069x over previous
#include <cuda_runtime.h>
#include <math.h>

#define BS 8
#define QN 1000
#define NC 92
#define TN 300
#define QP1 1001
#define TP1 301
#define SCSZ (BS*QP1*TP1)          // 2,410,408
#define MTROW (QN+TN)              // 1300
#define CPL 10
#define CHUNK 250
#define NSTEP 1032                 // = 8*129 >= QN+30 drain
#define SKROW 1048                 // >= NSTEP + 8 prefetch
#define FULLM 0xffffffffu
#define NEGINF (-INFINITY)
// slot of (strip col k, lane l) within a 320-float step row (float2-paired)
#define SLOT(k,l) (((k) >> 1) * 64 + (l) * 2 + ((k) & 1))

#define NMAIN (BS*QN*30)           // post_kernel main cells
#define NCOL0 (BS*QP1)             // post_kernel col-0 boundary
#define NROW0 (BS*TN)              // post_kernel row-0 boundary (j>=1)

__device__ float2 g_sm[BS*QN];               // per-(b,q) softmax (max, sum)
__device__ float g_rwsk[BS*SKROW*320];       // rewards, skewed+paired
__device__ float g_scr[BS*SKROW*320];        // scores scratch, skewed+paired
__device__ unsigned g_pk2[BS*SKROW*32];      // 2-bit ptr codes
__device__ int g_lbl64;

// ---------------- label dtype detection ----------------
__global__ void detect_kernel(const unsigned* __restrict__ lbl_raw) {
    int allzero = 1;
    #pragma unroll
    for (int k = 1; k < 16; k += 2) allzero &= (lbl_raw[k] == 0u);
    g_lbl64 = allzero;
}

// ---------------- softmax stats: per-(b,q) max & sum ----------------
__global__ void stat_kernel(const float* __restrict__ logits) {
    int warpId = (blockIdx.x * blockDim.x + threadIdx.x) >> 5;
    int lane = threadIdx.x & 31;
    if (warpId >= BS * QN) return;
    const float* row = logits + warpId * NC;
    float v0 = (lane < NC)      ? row[lane]      : NEGINF;
    float v1 = (lane + 32 < NC) ? row[lane + 32] : NEGINF;
    float v2 = (lane + 64 < NC) ? row[lane + 64] : NEGINF;
    float m = fmaxf(v0, fmaxf(v1, v2));
    #pragma unroll
    for (int o = 16; o; o >>= 1) m = fmaxf(m, __shfl_xor_sync(FULLM, m, o));
    float e0 = (lane < NC)      ? expf(v0 - m) : 0.f;
    float e1 = (lane + 32 < NC) ? expf(v1 - m) : 0.f;
    float e2 = (lane + 64 < NC) ? expf(v2 - m) : 0.f;
    float s = e0 + e1 + e2;
    #pragma unroll
    for (int o = 16; o; o >>= 1) s += __shfl_xor_sync(FULLM, s, o);
    if (lane == 0) g_sm[warpId] = make_float2(m, s);
}

// ---------------- cost -> skewed paired rewards ----------------
__global__ void cost_kernel(const float* __restrict__ logits,
                            const float* __restrict__ pred_boxes,
                            const int* __restrict__ tgt_labels,
                            const float* __restrict__ tgt_boxes) {
    int idx = blockIdx.x * blockDim.x + threadIdx.x;
    if (idx >= BS * QN * TN) return;
    int t = idx % TN;
    int bq = idx / TN;
    int b = bq / QN;
    int r = (bq % QN) + 1;

    float4 pb = ((const float4*)pred_boxes)[bq];
    float4 tb = ((const float4*)tgt_boxes)[b * TN + t];
    int li = b * TN + t;
    int lbl = g_lbl64 ? tgt_labels[li * 2] : tgt_labels[li];
    lbl = max(0, min(NC - 1, lbl));
    float2 ms = g_sm[bq];
    float p = expf(logits[bq * NC + lbl] - ms.x) / ms.y;   // same bits as e/s

    float l1 = fabsf(pb.x - tb.x) + fabsf(pb.y - tb.y) +
               fabsf(pb.z - tb.z) + fabsf(pb.w - tb.w);

    float px1 = pb.x - 0.5f * pb.z, py1 = pb.y - 0.5f * pb.w;
    float px2 = pb.x + 0.5f * pb.z, py2 = pb.y + 0.5f * pb.w;
    float tx1 = tb.x - 0.5f * tb.z, ty1 = tb.y - 0.5f * tb.w;
    float tx2 = tb.x + 0.5f * tb.z, ty2 = tb.y + 0.5f * tb.w;

    float a1 = (px2 - px1) * (py2 - py1);
    float a2 = (tx2 - tx1) * (ty2 - ty1);
    float ltx = fmaxf(px1, tx1), lty = fmaxf(py1, ty1);
    float rbx = fminf(px2, tx2), rby = fminf(py2, ty2);
    float iw = fmaxf(rbx - ltx, 0.f), ih = fmaxf(rby - lty, 0.f);
    float inter = iw * ih;
    float uni = a1 + a2 - inter;
    float iou = inter / uni;
    float cx1 = fminf(px1, tx1), cy1 = fminf(py1, ty1);
    float cx2 = fmaxf(px2, tx2), cy2 = fmaxf(py2, ty2);
    float cw = fmaxf(cx2 - cx1, 0.f), ch = fmaxf(cy2 - cy1, 0.f);
    float ac = cw * ch;
    float giou = iou - (ac - uni) / ac;

    float cost = 5.0f * l1 - p - 2.0f * giou;
    int l = t / CPL, k = t % CPL;
    g_rwsk[(size_t)b * SKROW * 320 + (size_t)(r + l) * 320 + SLOT(k, l)] = 10000.0f - cost;
}

// ---------------- DP: one WARP per batch, wavefront, scores only ----------
__global__ void __launch_bounds__(32, 1) dp_kernel() {
    int b = blockIdx.x;
    int lane = threadIdx.x;

    const float2* rwsk = (const float2*)(g_rwsk + (size_t)b * SKROW * 320);
    float2* scr = (float2*)(g_scr + (size_t)b * SKROW * 320);

    float prev[CPL];
    #pragma unroll
    for (int k = 0; k < CPL; k++) prev[k] = 0.f;
    float h1 = 0.f, h2 = 0.f;

    float2 B0[5], B1[5], B2[5], B3[5], B4[5], B5[5], B6[5], B7[5];

    #define LOADBUF(BUF, S)                                                     \
    {                                                                           \
        const float2* pp = rwsk + (size_t)(S) * 160 + lane;                     \
        _Pragma("unroll")                                                       \
        for (int q = 0; q < 5; q++) BUF[q] = pp[q * 32];                        \
    }

    LOADBUF(B0, 1) LOADBUF(B1, 2) LOADBUF(B2, 3) LOADBUF(B3, 4)
    LOADBUF(B4, 5) LOADBUF(B5, 6) LOADBUF(B6, 7) LOADBUF(B7, 8)

    #define STEP(S, BUF)                                                        \
    {                                                                           \
        int r = (S) - lane;                                                     \
        bool act = (lane < 30) && (r >= 1) && (r <= QN);                        \
        float X1 = __shfl_up_sync(FULLM, h1, 1);                                \
        float X2 = __shfl_up_sync(FULLM, h2, 1);                                \
        if (lane == 0) { X1 = NEGINF; X2 = 0.f; }                               \
        float rk[CPL];                                                          \
        _Pragma("unroll")                                                       \
        for (int q = 0; q < 5; q++) { rk[2*q] = BUF[q].x; rk[2*q+1] = BUF[q].y; } \
        LOADBUF(BUF, (S) + 8)                                                   \
        /* fused sequential prefix: 30 fma-pipe ops, dep ~= 9*4 cyc */          \
        float pf[CPL];                                                          \
        pf[0] = fmaxf(fmaxf(X2 + rk[0], prev[0]), X1);                          \
        _Pragma("unroll")                                                       \
        for (int k = 1; k < CPL; k++)                                           \
            pf[k] = fmaxf(fmaxf(prev[k-1] + rk[k], prev[k]), pf[k-1]);          \
        h2 = h1;                                                                \
        float2* dsc = scr + (size_t)(S) * 160 + lane;                           \
        _Pragma("unroll")                                                       \
        for (int q = 0; q < 5; q++) dsc[q * 32] = make_float2(pf[2*q], pf[2*q+1]); \
        if (act) {                                                              \
            _Pragma("unroll")                                                   \
            for (int k = 0; k < CPL; k++) prev[k] = pf[k];                      \
            h1 = pf[CPL-1];                                                     \
        } else {                                                                \
            h1 = 0.f;                                                           \
        }                                                                       \
    }

    #pragma unroll 1
    for (int s = 1; s <= NSTEP; s += 8) {
        STEP(s,     B0) STEP(s + 1, B1) STEP(s + 2, B2) STEP(s + 3, B3)
        STEP(s + 4, B4) STEP(s + 5, B5) STEP(s + 6, B6) STEP(s + 7, B7)
    }
    #undef STEP
    #undef LOADBUF
}

// ---------------- fused post: scores + pointers + codes + boundaries -------
__global__ void post_kernel(float* __restrict__ out) {
    int idx = blockIdx.x * blockDim.x + threadIdx.x;
    if (idx < NMAIN) {
        int l = idx % 30;
        int br = idx / 30;
        int r = (br % QN) + 1;
        int b = br / QN;

        const float* scr = g_scr + (size_t)b * SKROW * 320;
        const float* rwsk = g_rwsk + (size_t)b * SKROW * 320;
        size_t sc = (size_t)(r + l) * 320;
        size_t sp = (size_t)(r - 1 + l) * 320;

        float X2;
        if (l == 0 || r == 1) X2 = 0.f;
        else X2 = scr[(size_t)(r - 1 + l - 1) * 320 + SLOT(9, l - 1)];

        size_t rowoff = ((size_t)b * QP1 + r) * TP1 + 1 + l * CPL;
        float* dsts = out + rowoff;
        float* dstp = out + SCSZ + rowoff;
        unsigned word = 0;
        float pl = X2;
        #pragma unroll
        for (int k = 0; k < CPL; k++) {
            float rw = rwsk[sc + SLOT(k, l)];
            float pv = (r == 1) ? 0.f : scr[sp + SLOT(k, l)];
            float sn = scr[sc + SLOT(k, l)];
            float dg = pl + rw;
            unsigned e = (dg == sn) ? 0u : ((pv == sn) ? 1u : 2u);
            word |= e << (2 * k);
            dsts[k] = sn;
            dstp[k] = (e == 0u) ? 0.f : ((e == 1u) ? -1.f : 1.f);
            pl = pv;
        }
        g_pk2[(size_t)b * SKROW * 32 + (size_t)(r + l) * 32 + l] = word;
    } else if (idx < NMAIN + NCOL0) {
        int x = idx - NMAIN;
        int i = x % QP1;
        int b = x / QP1;
        size_t o = ((size_t)b * QP1 + i) * TP1;
        out[o] = 0.f;
        out[SCSZ + o] = (i == 0) ? 0.f : -1.f;
    } else if (idx < NMAIN + NCOL0 + NROW0) {
        int x = idx - NMAIN - NCOL0;
        int j = (x % TN) + 1;
        int b = x / TN;
        size_t o = (size_t)b * QP1 * TP1 + j;
        out[o] = 0.f;
        out[SCSZ + o] = 1.f;
    }
}

// ---------------- traceback: one warp per batch, chunked smem ----------
__global__ void __launch_bounds__(32, 1) tb_kernel(float* __restrict__ out) {
    __shared__ unsigned chunkBuf[(CHUNK + 30) * 32];   // 35.8 KB

    int b = blockIdx.x;
    int lane = threadIdx.x;
    const unsigned* pk2 = g_pk2 + (size_t)b * SKROW * 32;
    float* mt = out + 2 * (size_t)SCSZ + (size_t)b * MTROW * 2;
    int r = QN, c = TN, st = 0;

    #pragma unroll 1
    for (int kk = 0; kk < QN / CHUNK; kk++) {
        int hi = QN - kk * CHUNK;
        int lo = hi - (CHUNK - 1);
        const unsigned* src = pk2 + (size_t)lo * 32;
        #pragma unroll 4
        for (int x = lane; x < (CHUNK + 30) * 32; x += 32) chunkBuf[x] = src[x];
        __syncwarp();
        if (lane == 0) {
            while (st < MTROW && r >= lo) {
                int p;
                if (c == 0) {
                    p = -1;
                } else {
                    int ci = c - 1;
                    int l = ci / CPL;
                    unsigned wd = chunkBuf[(r + l - lo) * 32 + l];
                    int e = (wd >> (2 * (ci % CPL))) & 3;
                    p = (e == 0) ? 0 : ((e == 1) ? -1 : 1);
                }
                int nr = (p == 1) ? r : r - 1;
                int nc = (p == -1) ? c : c - 1;
                bool ismatch = (p == 0);
                int oidx = (MTROW - 1 - st) * 2;
                mt[oidx]     = ismatch ? (float)nr : -1.f;
                mt[oidx + 1] = ismatch ? (float)nc : -1.f;
                r = nr; c = nc; st++;
            }
        }
        __syncwarp();
    }
    if (lane == 0) {
        while (st < MTROW) {
            int oidx = (MTROW - 1 - st) * 2;
            mt[oidx] = -1.f;
            mt[oidx + 1] = -1.f;
            st++;
        }
    }
}

extern "C" void kernel_launch(void* const* d_in, const int* in_sizes, int n_in,
                              void* d_out, int out_size) {
    const float* pred_logits = (const float*)d_in[0];
    const float* pred_boxes  = (const float*)d_in[1];
    const int*   tgt_labels  = (const int*)d_in[2];
    const float* tgt_boxes   = (const float*)d_in[3];
    float* out = (float*)d_out;

    detect_kernel<<<1, 1>>>((const unsigned*)d_in[2]);
    stat_kernel<<<(BS * QN + 7) / 8, 256>>>(pred_logits);
    cost_kernel<<<(BS * QN * TN + 255) / 256, 256>>>(pred_logits, pred_boxes,
                                                     tgt_labels, tgt_boxes);
    dp_kernel<<<BS, 32>>>();
    post_kernel<<<(NMAIN + NCOL0 + NROW0 + 127) / 128, 128>>>(out);
    tb_kernel<<<BS, 32>>>(out);
}